// round 1
// baseline (speedup 1.0000x reference)
#include <cuda_runtime.h>
#include <cuda_bf16.h>

// Z[b,w,t] = sum_c Q[b,w,c] * ( K[b, w+t, c] + bias[c, t] )
// B=16, T=1024, C=128, K has 2T-1 = 2047 key positions.
//
// Tiling: 64x64 output tile per block (grid 16 x 16 x 16), 256 threads,
// 4x4 micro-tile per thread. Reduction over C in chunks of 32 staged in smem.
// Within a tile, K rows needed are the contiguous panel u = w0+t0 + s, s in [0,127).

#define BDIM_B 16
#define TDIM   1024
#define CDIM   128
#define KROWS  (2 * TDIM - 1)   // 2047

#define TW 64      // tile rows (w)
#define TT 64      // tile cols (t)
#define BC 32      // c-chunk

__global__ __launch_bounds__(256, 4)
void sw_mm3d_kernel(const float* __restrict__ Q,
                    const float* __restrict__ Km,
                    const float* __restrict__ bias,
                    float* __restrict__ Z)
{
    const int b  = blockIdx.z;
    const int w0 = blockIdx.y * TW;
    const int t0 = blockIdx.x * TT;

    __shared__ float sQ[TW][BC + 1];     // sQ[i][c]
    __shared__ float sK[128][BC + 1];    // sK[s][c], s = i + tau
    __shared__ float sB[BC][TT + 1];     // sB[c][tau]

    const int tid = threadIdx.x;
    const int ty  = tid >> 4;            // 0..15  -> i base
    const int tx  = tid & 15;            // 0..15  -> tau base

    float acc[4][4];
#pragma unroll
    for (int a = 0; a < 4; a++)
#pragma unroll
        for (int v = 0; v < 4; v++) acc[a][v] = 0.0f;

    const float* Qb = Q  + ((long)b * TDIM) * CDIM;
    const float* Kb = Km + ((long)b * KROWS) * CDIM;

    for (int cc = 0; cc < CDIM; cc += BC) {
        __syncthreads();

        // ---- stage Q tile: 64 rows x 32 c  (512 float4, 2 per thread) ----
#pragma unroll
        for (int r = 0; r < 2; r++) {
            int f    = tid + 256 * r;        // 0..511
            int row  = f >> 3;               // /8  -> 0..63
            int cvec = f & 7;                // float4 index within 32 floats
            float4 v = *reinterpret_cast<const float4*>(
                Qb + (long)(w0 + row) * CDIM + cc + cvec * 4);
            sQ[row][cvec * 4 + 0] = v.x;
            sQ[row][cvec * 4 + 1] = v.y;
            sQ[row][cvec * 4 + 2] = v.z;
            sQ[row][cvec * 4 + 3] = v.w;
        }

        // ---- stage K panel: 128 rows x 32 c (1024 float4, 4 per thread) ----
#pragma unroll
        for (int r = 0; r < 4; r++) {
            int f    = tid + 256 * r;        // 0..1023
            int s    = f >> 3;               // 0..127
            int cvec = f & 7;
            int u    = w0 + t0 + s;
            float4 v = make_float4(0.f, 0.f, 0.f, 0.f);
            if (u < KROWS) {
                v = *reinterpret_cast<const float4*>(
                    Kb + (long)u * CDIM + cc + cvec * 4);
            }
            sK[s][cvec * 4 + 0] = v.x;
            sK[s][cvec * 4 + 1] = v.y;
            sK[s][cvec * 4 + 2] = v.z;
            sK[s][cvec * 4 + 3] = v.w;
        }

        // ---- stage bias tile: 32 c x 64 tau (512 float4, 2 per thread) ----
#pragma unroll
        for (int r = 0; r < 2; r++) {
            int f    = tid + 256 * r;        // 0..511
            int crow = f >> 4;               // /16 -> 0..31
            int tvec = f & 15;               // float4 index within 64 floats
            float4 v = *reinterpret_cast<const float4*>(
                bias + (long)(cc + crow) * TDIM + t0 + tvec * 4);
            sB[crow][tvec * 4 + 0] = v.x;
            sB[crow][tvec * 4 + 1] = v.y;
            sB[crow][tvec * 4 + 2] = v.z;
            sB[crow][tvec * 4 + 3] = v.w;
        }

        __syncthreads();

        // ---- compute ----
#pragma unroll 4
        for (int c = 0; c < BC; c++) {
            float q[4], kk[7], bb[4];
#pragma unroll
            for (int a = 0; a < 4; a++) q[a] = sQ[ty + 16 * a][c];
#pragma unroll
            for (int m = 0; m < 7; m++) kk[m] = sK[ty + tx + 16 * m][c];
#pragma unroll
            for (int v = 0; v < 4; v++) bb[v] = sB[c][tx + 16 * v];
#pragma unroll
            for (int a = 0; a < 4; a++)
#pragma unroll
                for (int v = 0; v < 4; v++)
                    acc[a][v] = fmaf(q[a], kk[a + v] + bb[v], acc[a][v]);
        }
    }

    // ---- epilogue: Z[b, w0+i, t0+tau] ----
    float* Zb = Z + ((long)b * TDIM) * TDIM;
#pragma unroll
    for (int a = 0; a < 4; a++) {
        int i = ty + 16 * a;
        float* zrow = Zb + (long)(w0 + i) * TDIM + t0;
#pragma unroll
        for (int v = 0; v < 4; v++) {
            zrow[tx + 16 * v] = acc[a][v];
        }
    }
}

extern "C" void kernel_launch(void* const* d_in, const int* in_sizes, int n_in,
                              void* d_out, int out_size)
{
    const float* Q    = (const float*)d_in[0];   // (16, 1024, 128)
    const float* Km   = (const float*)d_in[1];   // (16, 2047, 128)
    const float* bias = (const float*)d_in[2];   // (1, 1, 128, 1024)
    float* Z          = (float*)d_out;           // (16, 1024, 1024)

    dim3 grid(TDIM / TT, TDIM / TW, BDIM_B);     // (16, 16, 16)
    dim3 block(256);
    sw_mm3d_kernel<<<grid, block>>>(Q, Km, bias, Z);
}

// round 3
// speedup vs baseline: 1.0936x; 1.0936x over previous
#include <cuda_runtime.h>
#include <cuda_bf16.h>
#include <cstdint>

// Z[b,w,t] = sum_c Q[b,w,c] * ( K[b,w+t,c] + bias[c,t] ),  B=16, T=1024, C=128.
//
// Per 128x128 output tile (b, w0, t0), u0 = w0 + t0:
//   P0[i,s] = sum_c Q[w0+i,c] K[u0+s,c]        (s in [0,128))
//   P1[i,s] = sum_c Q[w0+i,c] K[u0+128+s,c]    (s in [0,128), col 127 unused)
//   PB[i,s] = sum_c Q[w0+i,c] bias[c,t0+s]
//   Z[i,tau] = PB[i,tau] + (tau>=  0 branch) P0[i, i+tau]   (i+tau <128)
//                        + (else)            P1[i, i+tau-128]
// All GEMMs: mma.sync m16n8k16 bf16, 3-pass hi/lo fp32-split, fp32 accum.

#define TDIM   1024
#define CDIM   128
#define KROWS  2047
#define NTHREADS 512

// smem layout (bytes). bf16 buffers: 128 rows x 256B, XOR-swizzled 16B chunks.
#define OQH 0
#define OQL 32768
#define OBH 65536
#define OBL 98304
#define OZ  131072
#define ZSTRIDE 132
#define SMEM_BYTES (131072 + 128 * ZSTRIDE * 4)   // 198656

__device__ __forceinline__ void ldsm4(uint32_t addr, uint32_t& r0, uint32_t& r1,
                                      uint32_t& r2, uint32_t& r3) {
    asm volatile("ldmatrix.sync.aligned.m8n8.x4.shared.b16 {%0,%1,%2,%3}, [%4];"
                 : "=r"(r0), "=r"(r1), "=r"(r2), "=r"(r3) : "r"(addr));
}
__device__ __forceinline__ void mma16816(float* d, uint32_t a0, uint32_t a1,
                                         uint32_t a2, uint32_t a3,
                                         uint32_t b0, uint32_t b1) {
    asm volatile("mma.sync.aligned.m16n8k16.row.col.f32.bf16.bf16.f32 "
                 "{%0,%1,%2,%3}, {%4,%5,%6,%7}, {%8,%9}, {%0,%1,%2,%3};"
                 : "+f"(d[0]), "+f"(d[1]), "+f"(d[2]), "+f"(d[3])
                 : "r"(a0), "r"(a1), "r"(a2), "r"(a3), "r"(b0), "r"(b1));
}
__device__ __forceinline__ uint32_t smem_u32(const void* p) {
    uint32_t a;
    asm("{ .reg .u64 t; cvta.to.shared.u64 t, %1; cvt.u32.u64 %0, t; }" : "=r"(a) : "l"(p));
    return a;
}

__device__ __forceinline__ uint32_t pack_hi_lo(float x, float y, uint32_t& lo_out) {
    __nv_bfloat16 hx = __float2bfloat16(x);
    __nv_bfloat16 hy = __float2bfloat16(y);
    __nv_bfloat16 lx = __float2bfloat16(x - __bfloat162float(hx));
    __nv_bfloat16 ly = __float2bfloat16(y - __bfloat162float(hy));
    __nv_bfloat162 h = __nv_bfloat162(hx, hy);
    __nv_bfloat162 l = __nv_bfloat162(lx, ly);
    lo_out = *reinterpret_cast<uint32_t*>(&l);
    return *reinterpret_cast<uint32_t*>(&h);
}

// store float4 (4 c-values) of row `row` at c = cv*4 into hi/lo bf16 buffers
__device__ __forceinline__ void st_hilo4(char* sm, int bufH, int bufL,
                                         int row, int cv, float4 v) {
    uint32_t l01, l23;
    uint32_t h01 = pack_hi_lo(v.x, v.y, l01);
    uint32_t h23 = pack_hi_lo(v.z, v.w, l23);
    int c2 = cv >> 1;                       // 16B chunk index 0..15
    uint32_t off = (uint32_t)(row * 256 + (((c2) ^ (row & 7)) << 4) + (cv & 1) * 8);
    *reinterpret_cast<uint2*>(sm + bufH + off) = make_uint2(h01, h23);
    *reinterpret_cast<uint2*>(sm + bufL + off) = make_uint2(l01, l23);
}

__global__ __launch_bounds__(NTHREADS, 1)
void sw_hmma_kernel(const float* __restrict__ Q,
                    const float* __restrict__ Km,
                    const float* __restrict__ bias,
                    float* __restrict__ Z)
{
    extern __shared__ char smem[];
    const uint32_t sb = smem_u32(smem);
    float* zb = reinterpret_cast<float*>(smem + OZ);

    const int tid  = threadIdx.x;
    const int wid  = tid >> 5;
    const int lane = tid & 31;
    const int wr   = wid >> 2;          // warp row 0..3  -> rows [wr*32, +32)
    const int wc   = wid & 3;           // warp col 0..3  -> cols [wc*32, +32)

    const int b  = blockIdx.z;
    const int w0 = blockIdx.y * 128;
    const int t0 = blockIdx.x * 128;
    const int u0 = w0 + t0;

    const float* Qb = Q  + ((size_t)b * TDIM) * CDIM;
    const float* Kb = Km + ((size_t)b * KROWS) * CDIM;

    // ---- lane-invariant ldmatrix address components ----
    const uint32_t rx   = lane & 7;
    const uint32_t aC2  = lane >> 4;            // 0/1
    const uint32_t bC2  = (lane >> 3) & 1;      // 0/1
    uint32_t aRow[2], bRow[2];
#pragma unroll
    for (int mt = 0; mt < 2; mt++)
        aRow[mt] = (uint32_t)((wr * 32 + mt * 16 + (lane & 15)) * 256);
#pragma unroll
    for (int p = 0; p < 2; p++)
        bRow[p] = (uint32_t)((wc * 32 + p * 16 + ((lane >> 4) << 3) + (lane & 7)) * 256);

    // epilogue fragment coords
    const int er = lane >> 2;
    const int ec = (lane & 3) * 2;

    float acc[2][4][4];

#define ZERO_ACC() do {                                                      \
    _Pragma("unroll") for (int _m = 0; _m < 2; _m++)                         \
    _Pragma("unroll") for (int _n = 0; _n < 4; _n++)                         \
    _Pragma("unroll") for (int _e = 0; _e < 4; _e++) acc[_m][_n][_e] = 0.f;  \
} while (0)

#define GPASS(ABASE, BBASE) do {                                             \
    _Pragma("unroll")                                                        \
    for (int st = 0; st < 8; st++) {                                         \
        uint32_t kc = 2u * (uint32_t)st;                                     \
        uint32_t a0,a1,a2,a3,a4,a5,a6,a7;                                    \
        ldsm4((ABASE) + aRow[0] + (((kc + aC2) ^ rx) << 4), a0,a1,a2,a3);    \
        ldsm4((ABASE) + aRow[1] + (((kc + aC2) ^ rx) << 4), a4,a5,a6,a7);    \
        uint32_t b0,b1,b2,b3,b4,b5,b6,b7;                                    \
        ldsm4((BBASE) + bRow[0] + (((kc + bC2) ^ rx) << 4), b0,b1,b2,b3);    \
        ldsm4((BBASE) + bRow[1] + (((kc + bC2) ^ rx) << 4), b4,b5,b6,b7);    \
        mma16816(acc[0][0], a0,a1,a2,a3, b0,b1);                             \
        mma16816(acc[0][1], a0,a1,a2,a3, b2,b3);                             \
        mma16816(acc[0][2], a0,a1,a2,a3, b4,b5);                             \
        mma16816(acc[0][3], a0,a1,a2,a3, b6,b7);                             \
        mma16816(acc[1][0], a4,a5,a6,a7, b0,b1);                             \
        mma16816(acc[1][1], a4,a5,a6,a7, b2,b3);                             \
        mma16816(acc[1][2], a4,a5,a6,a7, b4,b5);                             \
        mma16816(acc[1][3], a4,a5,a6,a7, b6,b7);                             \
    }                                                                        \
} while (0)

#define GEMM3() do {                                                         \
    ZERO_ACC();                                                              \
    GPASS(sb + OQH, sb + OBH);                                               \
    GPASS(sb + OQH, sb + OBL);                                               \
    GPASS(sb + OQL, sb + OBH);                                               \
} while (0)

    // ================= stage Q (hi/lo) =================
    for (int idx = tid; idx < 128 * 32; idx += NTHREADS) {
        int row = idx >> 5, cv = idx & 31;
        float4 v = *reinterpret_cast<const float4*>(Qb + (size_t)(w0 + row) * CDIM + cv * 4);
        st_hilo4(smem, OQH, OQL, row, cv, v);
    }

    // ================= stage bias -> B buffers =================
    // thread t: row tau = t>>2, c in [ (t&3)*32, +32 )
    {
        const int tau = tid >> 2;
        const int cb  = (tid & 3) * 32;
        float f[32];
#pragma unroll
        for (int j = 0; j < 32; j++)
            f[j] = __ldg(bias + (size_t)(cb + j) * TDIM + t0 + tau);
#pragma unroll
        for (int j = 0; j < 16; j++) {
            uint32_t lo;
            uint32_t hi = pack_hi_lo(f[2 * j], f[2 * j + 1], lo);
            int c = cb + 2 * j;                      // bf16 col
            int c2 = c >> 3;                         // 16B chunk
            uint32_t off = (uint32_t)(tau * 256 + ((c2 ^ (tau & 7)) << 4) + ((c * 2) & 15));
            *reinterpret_cast<uint32_t*>(smem + OBH + off) = hi;
            *reinterpret_cast<uint32_t*>(smem + OBL + off) = lo;
        }
    }
    __syncthreads();

    // ================= GEMM PB, assign into Zbuf =================
    GEMM3();
    __syncthreads();            // everyone done reading B before Zbuf reuse rules; (Zbuf untouched yet)
#pragma unroll
    for (int mt = 0; mt < 2; mt++)
#pragma unroll
        for (int nt = 0; nt < 4; nt++)
#pragma unroll
            for (int e = 0; e < 4; e++) {
                int i = wr * 32 + mt * 16 + er + ((e & 2) ? 8 : 0);
                int s = wc * 32 + nt * 8 + ec + (e & 1);
                zb[i * ZSTRIDE + s] = acc[mt][nt][e];
            }
    __syncthreads();

    // ================= K chunk 0: GEMM P0, scatter-add =================
    for (int idx = tid; idx < 128 * 32; idx += NTHREADS) {
        int row = idx >> 5, cv = idx & 31;
        int u = u0 + row;
        float4 v = *reinterpret_cast<const float4*>(Kb + (size_t)u * CDIM + cv * 4);
        st_hilo4(smem, OBH, OBL, row, cv, v);
    }
    __syncthreads();
    GEMM3();
#pragma unroll
    for (int mt = 0; mt < 2; mt++)
#pragma unroll
        for (int nt = 0; nt < 4; nt++)
#pragma unroll
            for (int e = 0; e < 4; e++) {
                int i = wr * 32 + mt * 16 + er + ((e & 2) ? 8 : 0);
                int s = wc * 32 + nt * 8 + ec + (e & 1);
                int tau = s - i;
                if (tau >= 0) zb[i * ZSTRIDE + tau] += acc[mt][nt][e];
            }
    __syncthreads();

    // ================= K chunk 1: GEMM P1, scatter-add =================
    for (int idx = tid; idx < 128 * 32; idx += NTHREADS) {
        int row = idx >> 5, cv = idx & 31;
        int u = u0 + 128 + row;
        if (u > 2046) u = 2046;                    // row 127 of chunk1 is never read
        float4 v = *reinterpret_cast<const float4*>(Kb + (size_t)u * CDIM + cv * 4);
        st_hilo4(smem, OBH, OBL, row, cv, v);
    }
    __syncthreads();
    GEMM3();
#pragma unroll
    for (int mt = 0; mt < 2; mt++)
#pragma unroll
        for (int nt = 0; nt < 4; nt++)
#pragma unroll
            for (int e = 0; e < 4; e++) {
                int i = wr * 32 + mt * 16 + er + ((e & 2) ? 8 : 0);
                int s = wc * 32 + nt * 8 + ec + (e & 1);
                int tau = s - i;
                if (tau < 0) zb[i * ZSTRIDE + tau + 128] += acc[mt][nt][e];
            }
    __syncthreads();

    // ================= writeout =================
    float* Zb = Z + ((size_t)b * TDIM + w0) * TDIM + t0;
    for (int idx = tid; idx < 128 * 32; idx += NTHREADS) {
        int row = idx >> 5, tv = idx & 31;
        float4 o = *reinterpret_cast<const float4*>(zb + row * ZSTRIDE + tv * 4);
        *reinterpret_cast<float4*>(Zb + (size_t)row * TDIM + tv * 4) = o;
    }

#undef GEMM3
#undef GPASS
#undef ZERO_ACC
}

extern "C" void kernel_launch(void* const* d_in, const int* in_sizes, int n_in,
                              void* d_out, int out_size)
{
    const float* Q    = (const float*)d_in[0];   // (16, 1024, 128)
    const float* Km   = (const float*)d_in[1];   // (16, 2047, 128)
    const float* bias = (const float*)d_in[2];   // (1, 1, 128, 1024)
    float* Z          = (float*)d_out;           // (16, 1024, 1024)

    cudaFuncSetAttribute(sw_hmma_kernel, cudaFuncAttributeMaxDynamicSharedMemorySize, SMEM_BYTES);
    dim3 grid(TDIM / 128, TDIM / 128, 16);       // (8, 8, 16) = 1024 CTAs
    sw_hmma_kernel<<<grid, NTHREADS, SMEM_BYTES>>>(Q, Km, bias, Z);
}

// round 4
// speedup vs baseline: 1.7036x; 1.5578x over previous
#include <cuda_runtime.h>
#include <cuda_bf16.h>
#include <cstdint>

// Z[b,w,t] = sum_c Q[b,w,c] * ( K[b,w+t,c] + bias[c,t] ),  B=16, T=1024, C=128.
//
// Per 128x128 output tile (b, w0, t0), u0 = w0 + t0:
//   PB[i,s] = sum_c Q[w0+i,c] bias[c,t0+s]        -> Z[i,s]
//   P0[i,s] = sum_c Q[w0+i,c] K[u0+s,c]           -> Z[i,s-i]      (s>=i)
//   P1[i,s] = sum_c Q[w0+i,c] K[u0+128+s,c]       -> Z[i,s-i+128]  (s<i)
// Each GEMM: single merged k-loop computing AhBh + AhBl + AlBh (bf16 hi/lo
// split, fp32 accum) -> rel err ~ 2^-16.

#define TDIM   1024
#define CDIM   128
#define KROWS  2047
#define NTHREADS 512

// smem layout (bytes). bf16 buffers: 128 rows x 256B, XOR-swizzled 16B chunks.
#define OQH 0
#define OQL 32768
#define OBH 65536
#define OBL 98304
#define OZ  131072
#define ZSTRIDE 132
#define SMEM_BYTES (131072 + 128 * ZSTRIDE * 4)   // 198656

__device__ __forceinline__ void ldsm4(uint32_t addr, uint32_t& r0, uint32_t& r1,
                                      uint32_t& r2, uint32_t& r3) {
    asm volatile("ldmatrix.sync.aligned.m8n8.x4.shared.b16 {%0,%1,%2,%3}, [%4];"
                 : "=r"(r0), "=r"(r1), "=r"(r2), "=r"(r3) : "r"(addr));
}
__device__ __forceinline__ void mma16816(float* d, uint32_t a0, uint32_t a1,
                                         uint32_t a2, uint32_t a3,
                                         uint32_t b0, uint32_t b1) {
    asm volatile("mma.sync.aligned.m16n8k16.row.col.f32.bf16.bf16.f32 "
                 "{%0,%1,%2,%3}, {%4,%5,%6,%7}, {%8,%9}, {%0,%1,%2,%3};"
                 : "+f"(d[0]), "+f"(d[1]), "+f"(d[2]), "+f"(d[3])
                 : "r"(a0), "r"(a1), "r"(a2), "r"(a3), "r"(b0), "r"(b1));
}
__device__ __forceinline__ uint32_t smem_u32(const void* p) {
    uint32_t a;
    asm("{ .reg .u64 t; cvta.to.shared.u64 t, %1; cvt.u32.u64 %0, t; }" : "=r"(a) : "l"(p));
    return a;
}

__device__ __forceinline__ uint32_t pack_hi_lo(float x, float y, uint32_t& lo_out) {
    __nv_bfloat16 hx = __float2bfloat16(x);
    __nv_bfloat16 hy = __float2bfloat16(y);
    __nv_bfloat16 lx = __float2bfloat16(x - __bfloat162float(hx));
    __nv_bfloat16 ly = __float2bfloat16(y - __bfloat162float(hy));
    __nv_bfloat162 h = __nv_bfloat162(hx, hy);
    __nv_bfloat162 l = __nv_bfloat162(lx, ly);
    lo_out = *reinterpret_cast<uint32_t*>(&l);
    return *reinterpret_cast<uint32_t*>(&h);
}

// store float4 (4 c-values) of row `row` at c = cv*4 into hi/lo bf16 buffers
__device__ __forceinline__ void st_hilo4(char* sm, int bufH, int bufL,
                                         int row, int cv, float4 v) {
    uint32_t l01, l23;
    uint32_t h01 = pack_hi_lo(v.x, v.y, l01);
    uint32_t h23 = pack_hi_lo(v.z, v.w, l23);
    int c2 = cv >> 1;                       // 16B chunk index 0..15
    uint32_t off = (uint32_t)(row * 256 + (((c2) ^ (row & 7)) << 4) + (cv & 1) * 8);
    *reinterpret_cast<uint2*>(sm + bufH + off) = make_uint2(h01, h23);
    *reinterpret_cast<uint2*>(sm + bufL + off) = make_uint2(l01, l23);
}

__global__ __launch_bounds__(NTHREADS, 1)
void sw_hmma_kernel(const float* __restrict__ Q,
                    const float* __restrict__ Km,
                    const float* __restrict__ bias,
                    float* __restrict__ Z)
{
    extern __shared__ char smem[];
    const uint32_t sb = smem_u32(smem);
    float* zb = reinterpret_cast<float*>(smem + OZ);

    const int tid  = threadIdx.x;
    const int wid  = tid >> 5;
    const int lane = tid & 31;
    const int wr   = wid >> 2;          // warp row 0..3  -> rows [wr*32, +32)
    const int wc   = wid & 3;           // warp col 0..3  -> cols [wc*32, +32)

    const int b  = blockIdx.z;
    const int w0 = blockIdx.y * 128;
    const int t0 = blockIdx.x * 128;
    const int u0 = w0 + t0;

    const float* Qb = Q  + ((size_t)b * TDIM) * CDIM;
    const float* Kb = Km + ((size_t)b * KROWS) * CDIM;

    // prefetch row/cv for the 8 per-thread K float4s
    const int pRow = tid >> 5;          // + 16*r
    const int pCv  = tid & 31;

    // ---- lane-invariant ldmatrix address components ----
    const uint32_t rx   = lane & 7;
    const uint32_t aC2  = lane >> 4;            // 0/1
    const uint32_t bC2  = (lane >> 3) & 1;      // 0/1
    uint32_t aRow[2], bRow[2];
#pragma unroll
    for (int mt = 0; mt < 2; mt++)
        aRow[mt] = (uint32_t)((wr * 32 + mt * 16 + (lane & 15)) * 256);
#pragma unroll
    for (int p = 0; p < 2; p++)
        bRow[p] = (uint32_t)((wc * 32 + p * 16 + ((lane >> 4) << 3) + (lane & 7)) * 256);

    // epilogue fragment coords
    const int er = lane >> 2;
    const int ec = (lane & 3) * 2;

    float acc[2][4][4];

#define ZERO_ACC() do {                                                      \
    _Pragma("unroll") for (int _m = 0; _m < 2; _m++)                         \
    _Pragma("unroll") for (int _n = 0; _n < 4; _n++)                         \
    _Pragma("unroll") for (int _e = 0; _e < 4; _e++) acc[_m][_n][_e] = 0.f;  \
} while (0)

    // merged 3-pass GEMM: per kstep 8 LDSM + 24 MMA, all into the same acc
#define GEMM_MERGED() do {                                                   \
    ZERO_ACC();                                                              \
    _Pragma("unroll")                                                        \
    for (int st = 0; st < 8; st++) {                                         \
        uint32_t kc = 2u * (uint32_t)st;                                     \
        uint32_t aoff = ((kc + aC2) ^ rx) << 4;                              \
        uint32_t boff = ((kc + bC2) ^ rx) << 4;                              \
        uint32_t ah0,ah1,ah2,ah3,ah4,ah5,ah6,ah7;                            \
        uint32_t al0,al1,al2,al3,al4,al5,al6,al7;                            \
        uint32_t bh0,bh1,bh2,bh3,bh4,bh5,bh6,bh7;                            \
        uint32_t bl0,bl1,bl2,bl3,bl4,bl5,bl6,bl7;                            \
        ldsm4(sb + OQH + aRow[0] + aoff, ah0,ah1,ah2,ah3);                   \
        ldsm4(sb + OQH + aRow[1] + aoff, ah4,ah5,ah6,ah7);                   \
        ldsm4(sb + OQL + aRow[0] + aoff, al0,al1,al2,al3);                   \
        ldsm4(sb + OQL + aRow[1] + aoff, al4,al5,al6,al7);                   \
        ldsm4(sb + OBH + bRow[0] + boff, bh0,bh1,bh2,bh3);                   \
        ldsm4(sb + OBH + bRow[1] + boff, bh4,bh5,bh6,bh7);                   \
        ldsm4(sb + OBL + bRow[0] + boff, bl0,bl1,bl2,bl3);                   \
        ldsm4(sb + OBL + bRow[1] + boff, bl4,bl5,bl6,bl7);                   \
        /* Ah * Bh */                                                        \
        mma16816(acc[0][0], ah0,ah1,ah2,ah3, bh0,bh1);                       \
        mma16816(acc[0][1], ah0,ah1,ah2,ah3, bh2,bh3);                       \
        mma16816(acc[0][2], ah0,ah1,ah2,ah3, bh4,bh5);                       \
        mma16816(acc[0][3], ah0,ah1,ah2,ah3, bh6,bh7);                       \
        mma16816(acc[1][0], ah4,ah5,ah6,ah7, bh0,bh1);                       \
        mma16816(acc[1][1], ah4,ah5,ah6,ah7, bh2,bh3);                       \
        mma16816(acc[1][2], ah4,ah5,ah6,ah7, bh4,bh5);                       \
        mma16816(acc[1][3], ah4,ah5,ah6,ah7, bh6,bh7);                       \
        /* Ah * Bl */                                                        \
        mma16816(acc[0][0], ah0,ah1,ah2,ah3, bl0,bl1);                       \
        mma16816(acc[0][1], ah0,ah1,ah2,ah3, bl2,bl3);                       \
        mma16816(acc[0][2], ah0,ah1,ah2,ah3, bl4,bl5);                       \
        mma16816(acc[0][3], ah0,ah1,ah2,ah3, bl6,bl7);                       \
        mma16816(acc[1][0], ah4,ah5,ah6,ah7, bl0,bl1);                       \
        mma16816(acc[1][1], ah4,ah5,ah6,ah7, bl2,bl3);                       \
        mma16816(acc[1][2], ah4,ah5,ah6,ah7, bl4,bl5);                       \
        mma16816(acc[1][3], ah4,ah5,ah6,ah7, bl6,bl7);                       \
        /* Al * Bh */                                                        \
        mma16816(acc[0][0], al0,al1,al2,al3, bh0,bh1);                       \
        mma16816(acc[0][1], al0,al1,al2,al3, bh2,bh3);                       \
        mma16816(acc[0][2], al0,al1,al2,al3, bh4,bh5);                       \
        mma16816(acc[0][3], al0,al1,al2,al3, bh6,bh7);                       \
        mma16816(acc[1][0], al4,al5,al6,al7, bh0,bh1);                       \
        mma16816(acc[1][1], al4,al5,al6,al7, bh2,bh3);                       \
        mma16816(acc[1][2], al4,al5,al6,al7, bh4,bh5);                       \
        mma16816(acc[1][3], al4,al5,al6,al7, bh6,bh7);                       \
    }                                                                        \
} while (0)

    // ========== prefetch K chunk 0 into registers ==========
    float4 kreg[8];
#pragma unroll
    for (int r = 0; r < 8; r++)
        kreg[r] = *reinterpret_cast<const float4*>(
            Kb + (size_t)(u0 + pRow + 16 * r) * CDIM + pCv * 4);

    // ========== stage Q (hi/lo) ==========
    for (int idx = tid; idx < 128 * 32; idx += NTHREADS) {
        int row = idx >> 5, cv = idx & 31;
        float4 v = *reinterpret_cast<const float4*>(Qb + (size_t)(w0 + row) * CDIM + cv * 4);
        st_hilo4(smem, OQH, OQL, row, cv, v);
    }

    // ========== stage bias -> B buffers ==========
    {
        const int tau = tid >> 2;
        const int cb  = (tid & 3) * 32;
        float f[32];
#pragma unroll
        for (int j = 0; j < 32; j++)
            f[j] = __ldg(bias + (size_t)(cb + j) * TDIM + t0 + tau);
#pragma unroll
        for (int j = 0; j < 16; j++) {
            uint32_t lo;
            uint32_t hi = pack_hi_lo(f[2 * j], f[2 * j + 1], lo);
            int c = cb + 2 * j;                      // bf16 col
            int c2 = c >> 3;                         // 16B chunk
            uint32_t off = (uint32_t)(tau * 256 + ((c2 ^ (tau & 7)) << 4) + ((c * 2) & 15));
            *reinterpret_cast<uint32_t*>(smem + OBH + off) = hi;
            *reinterpret_cast<uint32_t*>(smem + OBL + off) = lo;
        }
    }
    __syncthreads();

    // ========== GEMM PB ==========
    GEMM_MERGED();
    __syncthreads();                  // all warps done reading bias B

    // convert K0 regs -> B buffers (frees kreg), then prefetch K1, then scatter PB
#pragma unroll
    for (int r = 0; r < 8; r++)
        st_hilo4(smem, OBH, OBL, pRow + 16 * r, pCv, kreg[r]);
#pragma unroll
    for (int r = 0; r < 8; r++) {
        int u = u0 + 128 + pRow + 16 * r;
        if (u > 2046) u = 2046;       // row 127 of chunk1 is never read
        kreg[r] = *reinterpret_cast<const float4*>(Kb + (size_t)u * CDIM + pCv * 4);
    }
#pragma unroll
    for (int mt = 0; mt < 2; mt++)
#pragma unroll
        for (int nt = 0; nt < 4; nt++)
#pragma unroll
            for (int e = 0; e < 4; e++) {
                int i = wr * 32 + mt * 16 + er + ((e & 2) ? 8 : 0);
                int s = wc * 32 + nt * 8 + ec + (e & 1);
                zb[i * ZSTRIDE + s] = acc[mt][nt][e];
            }
    __syncthreads();

    // ========== GEMM P0 (K1 loads in flight) ==========
    GEMM_MERGED();
    __syncthreads();                  // all warps done reading K0 B

    // convert K1 -> B buffers, scatter P0
#pragma unroll
    for (int r = 0; r < 8; r++)
        st_hilo4(smem, OBH, OBL, pRow + 16 * r, pCv, kreg[r]);
#pragma unroll
    for (int mt = 0; mt < 2; mt++)
#pragma unroll
        for (int nt = 0; nt < 4; nt++)
#pragma unroll
            for (int e = 0; e < 4; e++) {
                int i = wr * 32 + mt * 16 + er + ((e & 2) ? 8 : 0);
                int s = wc * 32 + nt * 8 + ec + (e & 1);
                int tau = s - i;
                if (tau >= 0) zb[i * ZSTRIDE + tau] += acc[mt][nt][e];
            }
    __syncthreads();

    // ========== GEMM P1 ==========
    GEMM_MERGED();
#pragma unroll
    for (int mt = 0; mt < 2; mt++)
#pragma unroll
        for (int nt = 0; nt < 4; nt++)
#pragma unroll
            for (int e = 0; e < 4; e++) {
                int i = wr * 32 + mt * 16 + er + ((e & 2) ? 8 : 0);
                int s = wc * 32 + nt * 8 + ec + (e & 1);
                int tau = s - i;
                if (tau < 0) zb[i * ZSTRIDE + tau + 128] += acc[mt][nt][e];
            }
    __syncthreads();

    // ========== writeout ==========
    float* Zb = Z + ((size_t)b * TDIM + w0) * TDIM + t0;
    for (int idx = tid; idx < 128 * 32; idx += NTHREADS) {
        int row = idx >> 5, tv = idx & 31;
        float4 o = *reinterpret_cast<const float4*>(zb + row * ZSTRIDE + tv * 4);
        *reinterpret_cast<float4*>(Zb + (size_t)row * TDIM + tv * 4) = o;
    }

#undef GEMM_MERGED
#undef ZERO_ACC
}

extern "C" void kernel_launch(void* const* d_in, const int* in_sizes, int n_in,
                              void* d_out, int out_size)
{
    const float* Q    = (const float*)d_in[0];   // (16, 1024, 128)
    const float* Km   = (const float*)d_in[1];   // (16, 2047, 128)
    const float* bias = (const float*)d_in[2];   // (1, 1, 128, 1024)
    float* Z          = (float*)d_out;           // (16, 1024, 1024)

    cudaFuncSetAttribute(sw_hmma_kernel, cudaFuncAttributeMaxDynamicSharedMemorySize, SMEM_BYTES);
    dim3 grid(TDIM / 128, TDIM / 128, 16);       // (8, 8, 16) = 1024 CTAs
    sw_hmma_kernel<<<grid, NTHREADS, SMEM_BYTES>>>(Q, Km, bias, Z);
}